// round 14
// baseline (speedup 1.0000x reference)
#include <cuda_runtime.h>
#include <math.h>
#include <stdint.h>

// GroupBRouter fused router — 3xTF32 mma.sync, double-buffered + reg-prefetch pipeline.
// logits = tokens(65536x1024) @ W_g^T(1024x64) + b_g ; softmax; floor; cap; top-2.
// B=16, N=4096, D=1024, E=64.

namespace {
constexpr int D      = 1024;
constexpr int E      = 64;
constexpr int BM     = 128;   // tokens per CTA
constexpr int BK     = 32;    // K chunk
constexpr int CHUNKS = D / BK;
constexpr int TPB    = 256;   // 8 warps; warp tile = 16 tokens x 64 experts
constexpr int AST    = 36;    // staging row stride; frag loads conflict-free (4r+tg banks)
constexpr int LST    = 65;    // epilogue scratch stride
constexpr int A_ELEMS = BM * AST;      // 4608
constexpr int B_ELEMS = E  * AST;      // 2304
constexpr int OFF_A0 = 0;
constexpr int OFF_A1 = A_ELEMS;
constexpr int OFF_B0 = 2 * A_ELEMS;
constexpr int OFF_B1 = 2 * A_ELEMS + B_ELEMS;
constexpr int BUF_FLOATS = 2 * A_ELEMS + 2 * B_ELEMS;    // 13824 floats = 55296 B
constexpr int SMEM_FLOATS = 2 * BUF_FLOATS;              // 110592 B total
}

__device__ __forceinline__ uint32_t cvt_tf32(float x) {
    uint32_t u; asm("cvt.rna.tf32.f32 %0, %1;" : "=r"(u) : "f"(x)); return u;
}
// 2-way tf32 split: x = hi + lo + O(2^-24 x)
__device__ __forceinline__ void split2(float x, float& hi, float& lo) {
    hi = __uint_as_float(cvt_tf32(x));
    lo = __uint_as_float(cvt_tf32(x - hi));
}
__device__ __forceinline__ void mma_tf32(float* d, const uint32_t* a, const uint32_t* b) {
    asm volatile(
        "mma.sync.aligned.m16n8k8.row.col.f32.tf32.tf32.f32 "
        "{%0,%1,%2,%3}, {%4,%5,%6,%7}, {%8,%9}, {%0,%1,%2,%3};"
        : "+f"(d[0]), "+f"(d[1]), "+f"(d[2]), "+f"(d[3])
        : "r"(a[0]), "r"(a[1]), "r"(a[2]), "r"(a[3]), "r"(b[0]), "r"(b[1]));
}

__global__ __launch_bounds__(TPB, 2)
void router_kernel(const float* __restrict__ tokens,
                   const int*   __restrict__ tsteps,
                   const float* __restrict__ Wg,
                   const float* __restrict__ bg,
                   float* __restrict__ out)
{
    extern __shared__ __align__(16) float smem[];
    float* Ls = smem;             // [BM][LST] epilogue scratch (reuses buffer 0)

    const int tid  = threadIdx.x;
    const int w    = tid >> 5;    // 0..7
    const int lane = tid & 31;
    const int r    = lane >> 2;   // 0..7
    const int tg   = lane & 3;    // 0..3
    const int m0   = blockIdx.x * BM;
    const int rb   = w * 16;      // warp's token-row base

    // staging thread mapping
    const int arow = tid >> 1;           // token row 0..127
    const int kh   = (tid & 1) * 16;     // A k-half
    const int erow = tid >> 2;           // expert row 0..63
    const int kq   = (tid & 3) * 8;      // B k-quarter

    const float* asrc_base = tokens + (size_t)(m0 + arow) * D + kh;
    const float* bsrc_base = Wg + (size_t)erow * D + kq;

    float acc[8][4];
    #pragma unroll
    for (int nt = 0; nt < 8; ++nt)
        #pragma unroll
        for (int i = 0; i < 4; ++i) acc[nt][i] = 0.f;

    float4 pa[4], pb[2];

    // ---- prologue: load + split + store chunk 0 into buffer 0 ----
    {
        #pragma unroll
        for (int it = 0; it < 4; ++it)
            pa[it] = *reinterpret_cast<const float4*>(asrc_base + it * 4);
        #pragma unroll
        for (int it = 0; it < 2; ++it)
            pb[it] = *reinterpret_cast<const float4*>(bsrc_base + it * 4);
        float* A0 = smem + OFF_A0 + arow * AST + kh;
        float* A1 = smem + OFF_A1 + arow * AST + kh;
        float* B0 = smem + OFF_B0 + erow * AST + kq;
        float* B1 = smem + OFF_B1 + erow * AST + kq;
        #pragma unroll
        for (int it = 0; it < 4; ++it) {
            float4 h, l;
            split2(pa[it].x, h.x, l.x); split2(pa[it].y, h.y, l.y);
            split2(pa[it].z, h.z, l.z); split2(pa[it].w, h.w, l.w);
            *reinterpret_cast<float4*>(A0 + it * 4) = h;
            *reinterpret_cast<float4*>(A1 + it * 4) = l;
        }
        #pragma unroll
        for (int it = 0; it < 2; ++it) {
            float4 h, l;
            split2(pb[it].x, h.x, l.x); split2(pb[it].y, h.y, l.y);
            split2(pb[it].z, h.z, l.z); split2(pb[it].w, h.w, l.w);
            *reinterpret_cast<float4*>(B0 + it * 4) = h;
            *reinterpret_cast<float4*>(B1 + it * 4) = l;
        }
    }
    __syncthreads();

    for (int ch = 0; ch < CHUNKS; ++ch) {
        const int  nb_idx = (ch + 1) & 1;
        float* buf = smem + (ch & 1) * BUF_FLOATS;
        float* nbuf = smem + nb_idx * BUF_FLOATS;
        const bool more = (ch + 1) < CHUNKS;

        // ---- prefetch chunk ch+1 into registers (latency hidden by MMAs) ----
        if (more) {
            const int k1 = (ch + 1) * BK;
            #pragma unroll
            for (int it = 0; it < 4; ++it)
                pa[it] = *reinterpret_cast<const float4*>(asrc_base + k1 + it * 4);
            #pragma unroll
            for (int it = 0; it < 2; ++it)
                pb[it] = *reinterpret_cast<const float4*>(bsrc_base + k1 + it * 4);
        }

        // ---- MMA phase on current buffer ----
        const float* As0 = buf + OFF_A0;
        const float* As1 = buf + OFF_A1;
        const float* Bs0 = buf + OFF_B0;
        const float* Bs1 = buf + OFF_B1;
        #pragma unroll
        for (int ks = 0; ks < 4; ++ks) {
            const int k = ks * 8;
            uint32_t A0r[4], A1r[4];
            {
                const float* p0 = As0 + k + tg;
                const float* p1 = As1 + k + tg;
                A0r[0] = __float_as_uint(p0[(rb + r)     * AST]);
                A0r[1] = __float_as_uint(p0[(rb + r + 8) * AST]);
                A0r[2] = __float_as_uint(p0[(rb + r)     * AST + 4]);
                A0r[3] = __float_as_uint(p0[(rb + r + 8) * AST + 4]);
                A1r[0] = __float_as_uint(p1[(rb + r)     * AST]);
                A1r[1] = __float_as_uint(p1[(rb + r + 8) * AST]);
                A1r[2] = __float_as_uint(p1[(rb + r)     * AST + 4]);
                A1r[3] = __float_as_uint(p1[(rb + r + 8) * AST + 4]);
            }
            uint32_t B0r[8][2], B1r[8][2];
            #pragma unroll
            for (int nt = 0; nt < 8; ++nt) {
                const int nb = nt * 8 + r;
                B0r[nt][0] = __float_as_uint(Bs0[nb * AST + k + tg]);
                B0r[nt][1] = __float_as_uint(Bs0[nb * AST + k + tg + 4]);
                B1r[nt][0] = __float_as_uint(Bs1[nb * AST + k + tg]);
                B1r[nt][1] = __float_as_uint(Bs1[nb * AST + k + tg + 4]);
            }
            #pragma unroll
            for (int nt = 0; nt < 8; ++nt) mma_tf32(acc[nt], A0r, B0r[nt]);  // hi*hi
            #pragma unroll
            for (int nt = 0; nt < 8; ++nt) mma_tf32(acc[nt], A0r, B1r[nt]);  // hi*lo
            #pragma unroll
            for (int nt = 0; nt < 8; ++nt) mma_tf32(acc[nt], A1r, B0r[nt]);  // lo*hi
        }

        // ---- split + store prefetched chunk into the other buffer ----
        if (more) {
            float* A0 = nbuf + OFF_A0 + arow * AST + kh;
            float* A1 = nbuf + OFF_A1 + arow * AST + kh;
            float* B0 = nbuf + OFF_B0 + erow * AST + kq;
            float* B1 = nbuf + OFF_B1 + erow * AST + kq;
            #pragma unroll
            for (int it = 0; it < 4; ++it) {
                float4 h, l;
                split2(pa[it].x, h.x, l.x); split2(pa[it].y, h.y, l.y);
                split2(pa[it].z, h.z, l.z); split2(pa[it].w, h.w, l.w);
                *reinterpret_cast<float4*>(A0 + it * 4) = h;
                *reinterpret_cast<float4*>(A1 + it * 4) = l;
            }
            #pragma unroll
            for (int it = 0; it < 2; ++it) {
                float4 h, l;
                split2(pb[it].x, h.x, l.x); split2(pb[it].y, h.y, l.y);
                split2(pb[it].z, h.z, l.z); split2(pb[it].w, h.w, l.w);
                *reinterpret_cast<float4*>(B0 + it * 4) = h;
                *reinterpret_cast<float4*>(B1 + it * 4) = l;
            }
        }
        __syncthreads();   // publishes STS(ch+1); also closes MMA reads of buf
    }

    // ---- write logits (+bias) to per-token scratch (buffer 0) ----
    #pragma unroll
    for (int nt = 0; nt < 8; ++nt) {
        const int c0 = nt * 8 + 2 * tg;
        const float b0 = __ldg(bg + c0);
        const float b1 = __ldg(bg + c0 + 1);
        Ls[(rb + r)     * LST + c0]     = acc[nt][0] + b0;
        Ls[(rb + r)     * LST + c0 + 1] = acc[nt][1] + b1;
        Ls[(rb + r + 8) * LST + c0]     = acc[nt][2] + b0;
        Ls[(rb + r + 8) * LST + c0 + 1] = acc[nt][3] + b1;
    }
    __syncthreads();

    // ---- per-token epilogue: threads 0..127 own one token each (R1-proven) ----
    if (tid < BM) {
        float* row = Ls + tid * LST;

        float mx = row[0];
        for (int j = 1; j < E; ++j) mx = fmaxf(mx, row[j]);
        float s = 0.f;
        for (int j = 0; j < E; ++j) {
            float e = expf(row[j] - mx);
            row[j] = e;
            s += e;
        }
        float inv = 1.0f / s;

        int   gtok = m0 + tid;
        float tn   = (float)tsteps[gtok >> 12] / 1000.0f;
        float cap  = 0.5f + 1.1f * tn;

        float Se = 0.f, Sh = 0.f;
        for (int j = 0; j < E; ++j) {
            float q  = 0.85f * (row[j] * inv) + 0.00234375f;   // floor: 0.85p + 0.15/64
            float ex = fmaxf(q - cap, 0.f);
            float cp = q - ex;
            Se += ex;
            Sh += fmaxf(cap - cp, 0.f);
            row[j] = cp;
        }
        float invSh = 1.0f / fmaxf(Sh, 1e-8f);

        float v1 = -INFINITY, v2 = -INFINITY;
        int   i1 = 0, i2 = 0;
        for (int j = 0; j < E; ++j) {
            float cp = row[j];
            float f  = cp + Se * (fmaxf(cap - cp, 0.f) * invSh);
            if (f > v1)      { v2 = v1; i2 = i1; v1 = f; i1 = j; }
            else if (f > v2) { v2 = f;  i2 = j; }
        }

        for (int j = 0; j < E; ++j) row[j] = 0.f;
        row[i1] = v1;
        row[i2] = v2;
    }
    __syncthreads();

    // ---- coalesced store of the 128x64 gate tile ----
    float* ob = out + (size_t)m0 * E;
    for (int i = tid; i < BM * E; i += TPB)
        ob[i] = Ls[(i >> 6) * LST + (i & 63)];
}

extern "C" void kernel_launch(void* const* d_in, const int* in_sizes, int n_in,
                              void* d_out, int out_size)
{
    const float* tokens = nullptr;
    const int*   tarr   = nullptr;
    const float* Wg     = nullptr;
    const float* bg     = nullptr;
    for (int i = 0; i < n_in; ++i) {
        switch (in_sizes[i]) {
            case 16 * 4096 * 1024: tokens = (const float*)d_in[i]; break;
            case 16:               tarr   = (const int*)d_in[i];   break;
            case 64 * 1024:        Wg     = (const float*)d_in[i]; break;
            case 64:               bg     = (const float*)d_in[i]; break;
        }
    }
    static int smem_set = 0;
    if (!smem_set) {
        cudaFuncSetAttribute(router_kernel,
                             cudaFuncAttributeMaxDynamicSharedMemorySize,
                             SMEM_FLOATS * (int)sizeof(float));
        smem_set = 1;
    }
    router_kernel<<<512, TPB, SMEM_FLOATS * sizeof(float)>>>(
        tokens, tarr, Wg, bg, (float*)d_out);
}